// round 6
// baseline (speedup 1.0000x reference)
#include <cuda_runtime.h>
#include <cuda_bf16.h>
#include <math.h>
#include <stdint.h>

#define NROWS 65536
#define KC 256
#define DH 256
#define NKSZ ((size_t)NROWS * KC)
#define EPSV 1e-6f
#define SIGMA_HI_V 10000.0f
#define TARGET_Z 1.3219281f   /* log2(5)-1 */
#define TARGET_U 2.3219281f   /* log2(5)   */
#define INF_F __int_as_float(0x7f800000)
#define CAL_ITERS 150
#define NPART 2048

// ---------------- scratch (device globals; no runtime allocation) ----------
__device__ float g_d[NKSZ];                 // 64MB distance matrix
__device__ uint4 g_mhi4[KC * 64];           // mu hi tf32-in-f32 (16B quads)
__device__ uint4 g_mlo4[KC * 64];           // mu lo tf32-in-f32
__device__ float g_m2[KC], g_ms[KC];
__device__ float g_rowp[(size_t)2 * NROWS * 5];  // per-colhalf row top5 partials
__device__ float g_rhoz[NROWS];
__device__ float g_sigz[NROWS];
__device__ float g_part1[(size_t)NPART * 5 * KC];   // [chunk][s][col]
__device__ float g_rhou[KC];
__device__ float g_sigu[KC];
__device__ float g_colsum[KC];

// ---------------- PTX helpers (baseline PTX only) ----------------------------
__device__ __forceinline__ uint32_t smem_u32(const void* p) {
    uint32_t a;
    asm("{ .reg .u64 t; cvta.to.shared.u64 t, %1; cvt.u32.u64 %0, t; }" : "=r"(a) : "l"(p));
    return a;
}

__device__ __forceinline__ uint32_t tf32u(float x) {
    uint32_t u;
    asm("cvt.rna.tf32.f32 %0, %1;" : "=r"(u) : "f"(x));
    return u;
}

__device__ __forceinline__ void ldmx4(uint32_t* r, uint32_t addr) {
    asm volatile("ldmatrix.sync.aligned.m8n8.x4.shared.b16 {%0,%1,%2,%3}, [%4];"
                 : "=r"(r[0]), "=r"(r[1]), "=r"(r[2]), "=r"(r[3]) : "r"(addr));
}

__device__ __forceinline__ void mma_tf32(float* d, const uint32_t* a, const uint32_t* b) {
    asm volatile(
        "mma.sync.aligned.m16n8k8.row.col.f32.tf32.tf32.f32 "
        "{%0,%1,%2,%3}, {%4,%5,%6,%7}, {%8,%9}, {%0,%1,%2,%3};"
        : "+f"(d[0]), "+f"(d[1]), "+f"(d[2]), "+f"(d[3])
        : "r"(a[0]), "r"(a[1]), "r"(a[2]), "r"(a[3]), "r"(b[0]), "r"(b[1]));
}

__device__ __forceinline__ void cpa16(uint32_t dst, const void* src) {
    asm volatile("cp.async.cg.shared.global [%0], [%1], 16;"
                 :: "r"(dst), "l"(__cvta_generic_to_global(src)));
}
__device__ __forceinline__ void cpa_commit() {
    asm volatile("cp.async.commit_group;");
}

// ---------------- K0: mu prep (hi/lo tf32 split + stats) ---------------------
__global__ void k_prep_mu(const float* __restrict__ mu) {
    int j = threadIdx.x;
    const float* r = mu + (size_t)j * DH;
    float m2 = 0.f, ms = 0.f;
    for (int i = 0; i < 64; i++) {
        float4 v = *(const float4*)(r + i * 4);
        float x[4] = {v.x, v.y, v.z, v.w};
        uint32_t hi[4], lo[4];
#pragma unroll
        for (int q = 0; q < 4; q++) {
            m2 = fmaf(x[q], x[q], m2);
            ms += x[q];
            hi[q] = tf32u(x[q]);
            lo[q] = tf32u(x[q] - __uint_as_float(hi[q]));
        }
        g_mhi4[j * 64 + i] = make_uint4(hi[0], hi[1], hi[2], hi[3]);
        g_mlo4[j * 64 + i] = make_uint4(lo[0], lo[1], lo[2], lo[3]);
    }
    g_m2[j] = m2;
    g_ms[j] = ms;
}

// ---------------- insertion helper ------------------------------------------
__device__ __forceinline__ void ins5(float v, float &t0, float &t1, float &t2,
                                     float &t3, float &t4) {
    if (v < t4) {
        if (v < t3) {
            t4 = t3;
            if (v < t2) {
                t3 = t2;
                if (v < t1) {
                    t2 = t1;
                    if (v < t0) { t1 = t0; t0 = v; } else t1 = v;
                } else t2 = v;
            } else t3 = v;
        } else t4 = v;
    }
}

// ---------------- K1: fused tf32-split GEMM ----------------------------------
// CTA tile 128x128, 512 threads = 16 warps (4 row x 4 col), warp tile 32x32.
// A (z): cp.async raw f32, tf32 hi/lo split in registers.
// B (mu): cp.async from pre-split g_mhi4/g_mlo4 (no cvt).
// K: 8 chunks of 32, 2-stage double buffer; 4 k8-steps/chunk; 3 passes hh+lh+hl.
#define LDS_T 36                      /* padded f32 row stride */
#define SB_HI 18432
#define SB_LO 36864
#define STAGE_SZ 55296
#define TILE_LD 132
#define ST_M2 110592
#define ST_MS 111104
#define ST_Z2 111616
#define ST_ZS 112128
#define GSMEM_TOTAL 112640

__device__ __forceinline__ void load_stage(uint32_t sbase, const float* z,
                                           int rowBase, int colBase, int ch, int t) {
#pragma unroll
    for (int i = 0; i < 2; i++) {
        int e = t + 512 * i;               // 0..1023
        int r = e >> 3, q = e & 7;
        cpa16(sbase + (uint32_t)(r * LDS_T + q * 4) * 4,
              z + (size_t)(rowBase + r) * DH + ch * 32 + q * 4);
    }
#pragma unroll
    for (int i = 0; i < 2; i++) {
        int e = t + 512 * i;
        int r = e >> 3, q = e & 7;
        cpa16(sbase + SB_HI + (uint32_t)(r * LDS_T + q * 4) * 4,
              &g_mhi4[(colBase + r) * 64 + ch * 8 + q]);
    }
#pragma unroll
    for (int i = 0; i < 2; i++) {
        int e = t + 512 * i;
        int r = e >> 3, q = e & 7;
        cpa16(sbase + SB_LO + (uint32_t)(r * LDS_T + q * 4) * 4,
              &g_mlo4[(colBase + r) * 64 + ch * 8 + q]);
    }
}

__global__ __launch_bounds__(512) void k_gemm(const float* __restrict__ z) {
    extern __shared__ char smem[];
    const uint32_t sb = smem_u32(smem);
    const int t = threadIdx.x;
    const int wid = t >> 5, lane = t & 31;
    const int wr = wid >> 2, wc = wid & 3;
    const int rowBase = blockIdx.x * 128;
    const int colBase = blockIdx.y * 128;

    float* s_m2 = (float*)(smem + ST_M2);
    float* s_ms = (float*)(smem + ST_MS);
    float* s_z2 = (float*)(smem + ST_Z2);
    float* s_zs = (float*)(smem + ST_ZS);
    if (t < 128) { s_m2[t] = g_m2[colBase + t]; s_ms[t] = g_ms[colBase + t]; }

    float acc[2][4][4];
#pragma unroll
    for (int mt = 0; mt < 2; mt++)
#pragma unroll
        for (int j = 0; j < 4; j++)
#pragma unroll
            for (int q = 0; q < 4; q++) acc[mt][j][q] = 0.f;

    float z2a[2][2] = {{0.f, 0.f}, {0.f, 0.f}};
    float zsa[2][2] = {{0.f, 0.f}, {0.f, 0.f}};

    const uint32_t a_off = ((uint32_t)(wr * 32 + (lane & 15)) * LDS_T +
                            ((lane >> 4) << 2)) * 4;
    const uint32_t b_off = ((uint32_t)(wc * 32 + ((lane >> 4) << 3) + (lane & 7)) * LDS_T +
                            ((lane & 8) >> 1)) * 4;

    load_stage(sb, z, rowBase, colBase, 0, t);
    cpa_commit();

#pragma unroll 1
    for (int ch = 0; ch < 8; ch++) {
        if (ch < 7) {
            load_stage(sb + ((ch + 1) & 1) * STAGE_SZ, z, rowBase, colBase, ch + 1, t);
            cpa_commit();
            asm volatile("cp.async.wait_group 1;");
        } else {
            asm volatile("cp.async.wait_group 0;");
        }
        __syncthreads();

        const uint32_t abase = sb + (ch & 1) * STAGE_SZ;

#pragma unroll
        for (int ks = 0; ks < 4; ks++) {
            const uint32_t kb = (uint32_t)ks * 32;
            uint32_t ar[2][4];
            ldmx4(ar[0], abase + a_off + kb);
            ldmx4(ar[1], abase + a_off + kb + 16 * LDS_T * 4);

            uint32_t ah[2][4], al[2][4];
#pragma unroll
            for (int mt = 0; mt < 2; mt++)
#pragma unroll
                for (int q = 0; q < 4; q++) {
                    float v = __uint_as_float(ar[mt][q]);
                    if (wc == 0) {
                        z2a[mt][q & 1] = fmaf(v, v, z2a[mt][q & 1]);
                        zsa[mt][q & 1] += v;
                    }
                    uint32_t h = tf32u(v);
                    ah[mt][q] = h;
                    al[mt][q] = tf32u(v - __uint_as_float(h));
                }

            uint32_t bh[2][4];
            ldmx4(bh[0], abase + SB_HI + b_off + kb);
            ldmx4(bh[1], abase + SB_HI + b_off + kb + 16 * LDS_T * 4);
#pragma unroll
            for (int mt = 0; mt < 2; mt++)
#pragma unroll
                for (int j = 0; j < 4; j++)
                    mma_tf32(acc[mt][j], ah[mt], &bh[j >> 1][(j & 1) * 2]);
#pragma unroll
            for (int mt = 0; mt < 2; mt++)
#pragma unroll
                for (int j = 0; j < 4; j++)
                    mma_tf32(acc[mt][j], al[mt], &bh[j >> 1][(j & 1) * 2]);

            uint32_t bl[2][4];
            ldmx4(bl[0], abase + SB_LO + b_off + kb);
            ldmx4(bl[1], abase + SB_LO + b_off + kb + 16 * LDS_T * 4);
#pragma unroll
            for (int mt = 0; mt < 2; mt++)
#pragma unroll
                for (int j = 0; j < 4; j++)
                    mma_tf32(acc[mt][j], ah[mt], &bl[j >> 1][(j & 1) * 2]);
        }
        __syncthreads();
    }

    // ---- per-row z stats (wc==0 warps own all 128 rows) ----------------------
    if (wc == 0) {
#pragma unroll
        for (int mt = 0; mt < 2; mt++)
#pragma unroll
            for (int h = 0; h < 2; h++) {
                z2a[mt][h] += __shfl_xor_sync(0xffffffffu, z2a[mt][h], 1);
                z2a[mt][h] += __shfl_xor_sync(0xffffffffu, z2a[mt][h], 2);
                zsa[mt][h] += __shfl_xor_sync(0xffffffffu, zsa[mt][h], 1);
                zsa[mt][h] += __shfl_xor_sync(0xffffffffu, zsa[mt][h], 2);
            }
        if ((lane & 3) == 0) {
#pragma unroll
            for (int mt = 0; mt < 2; mt++)
#pragma unroll
                for (int h = 0; h < 2; h++) {
                    int r = wr * 32 + mt * 16 + (lane >> 2) + h * 8;
                    s_z2[r] = z2a[mt][h];
                    s_zs[r] = zsa[mt][h];
                }
        }
    }
    __syncthreads();

    // ---- epilogue: d into smem tile (overwrites stage buffers) ---------------
    float* tile = (float*)smem;
    const float cterm = (float)DH * EPSV * EPSV;
#pragma unroll
    for (int mt = 0; mt < 2; mt++) {
        const int r0 = wr * 32 + mt * 16 + (lane >> 2);
        const float z2va = s_z2[r0], zsva = s_zs[r0];
        const float z2vb = s_z2[r0 + 8], zsvb = s_zs[r0 + 8];
#pragma unroll
        for (int nt = 0; nt < 4; nt++) {
            const int c0 = wc * 32 + nt * 8 + (lane & 3) * 2;
            float m20 = s_m2[c0], ms0 = s_ms[c0];
            float m21 = s_m2[c0 + 1], ms1 = s_ms[c0 + 1];
            float d00 = z2va + m20 - 2.f * acc[mt][nt][0] + 2.f * EPSV * (zsva - ms0) + cterm;
            float d01 = z2va + m21 - 2.f * acc[mt][nt][1] + 2.f * EPSV * (zsva - ms1) + cterm;
            float d10 = z2vb + m20 - 2.f * acc[mt][nt][2] + 2.f * EPSV * (zsvb - ms0) + cterm;
            float d11 = z2vb + m21 - 2.f * acc[mt][nt][3] + 2.f * EPSV * (zsvb - ms1) + cterm;
            tile[r0 * TILE_LD + c0]           = sqrtf(fmaxf(d00, 0.f));
            tile[r0 * TILE_LD + c0 + 1]       = sqrtf(fmaxf(d01, 0.f));
            tile[(r0 + 8) * TILE_LD + c0]     = sqrtf(fmaxf(d10, 0.f));
            tile[(r0 + 8) * TILE_LD + c0 + 1] = sqrtf(fmaxf(d11, 0.f));
        }
    }
    __syncthreads();

    // ---- coalesced store of d ------------------------------------------------
#pragma unroll
    for (int i = 0; i < 8; i++) {
        int e = t + 512 * i;          // 0..4095
        int row = e >> 5, c4 = e & 31;
        float4 v = *(const float4*)&tile[row * TILE_LD + c4 * 4];
        *(float4*)&g_d[(size_t)(rowBase + row) * KC + colBase + c4 * 4] = v;
    }

    // ---- row top-5 partials (this CTA's 128 cols; warp per 8 rows) ------------
#pragma unroll 1
    for (int rr = 0; rr < 8; rr++) {
        int lrow = wid * 8 + rr;
        float t0 = INF_F, t1 = INF_F, t2 = INF_F, t3 = INF_F, t4 = INF_F;
#pragma unroll
        for (int i = 0; i < 4; i++)
            ins5(tile[lrow * TILE_LD + lane + 32 * i], t0, t1, t2, t3, t4);
#pragma unroll
        for (int off = 16; off; off >>= 1) {
            float o0 = __shfl_xor_sync(0xffffffffu, t0, off);
            float o1 = __shfl_xor_sync(0xffffffffu, t1, off);
            float o2 = __shfl_xor_sync(0xffffffffu, t2, off);
            float o3 = __shfl_xor_sync(0xffffffffu, t3, off);
            float o4 = __shfl_xor_sync(0xffffffffu, t4, off);
            ins5(o0, t0, t1, t2, t3, t4);
            ins5(o1, t0, t1, t2, t3, t4);
            ins5(o2, t0, t1, t2, t3, t4);
            ins5(o3, t0, t1, t2, t3, t4);
            ins5(o4, t0, t1, t2, t3, t4);
        }
        if (lane == 0) {
            float* rp = g_rowp + (size_t)blockIdx.y * NROWS * 5 +
                        (size_t)(rowBase + lrow) * 5;
            rp[0] = t0; rp[1] = t1; rp[2] = t2; rp[3] = t3; rp[4] = t4;
        }
    }

    // ---- column top-5 partials (4 row-quarters of 32) --------------------------
    {
        int colL = t & 127, qtr = t >> 7;
        float t0 = INF_F, t1 = INF_F, t2 = INF_F, t3 = INF_F, t4 = INF_F;
#pragma unroll 4
        for (int r = 0; r < 32; r++)
            ins5(tile[(qtr * 32 + r) * TILE_LD + colL], t0, t1, t2, t3, t4);
        int p = blockIdx.x * 4 + qtr;
        float* pp = g_part1 + (size_t)p * 5 * KC + colBase + colL;
        pp[0 * KC] = t0; pp[1 * KC] = t1; pp[2 * KC] = t2;
        pp[3 * KC] = t3; pp[4 * KC] = t4;
    }
}

// ---------------- bisection (mirrors reference update rule) -----------------
__device__ __forceinline__ float calibrate(float a1, float a2, float a3, float a4,
                                           float target) {
    float mid0 = 0.f, mid1 = SIGMA_HI_V, sigma = 1.f;
#pragma unroll 1
    for (int it = 0; it < CAL_ITERS; it++) {
        float inv = __frcp_rn(sigma);
        float cur = 1.f + __expf(-a1 * inv) + __expf(-a2 * inv) +
                    __expf(-a3 * inv) + __expf(-a4 * inv);
        if (cur > target) mid1 = sigma; else mid0 = sigma;
        sigma = 0.5f * (mid0 + mid1);
    }
    return sigma;
}

// ---------------- K2: final column merge + sigma_u (+ colsum zero) ----------
__global__ void k_colfinal() {
    int col = blockIdx.x;
    int lane = threadIdx.x;  // 32 threads
    float t0 = INF_F, t1 = INF_F, t2 = INF_F, t3 = INF_F, t4 = INF_F;
    for (int b = lane; b < NPART; b += 32) {
        const float* pp = g_part1 + (size_t)b * 5 * KC + col;
#pragma unroll
        for (int s = 0; s < 5; s++) ins5(pp[s * KC], t0, t1, t2, t3, t4);
    }
#pragma unroll
    for (int off = 16; off; off >>= 1) {
        float o0 = __shfl_xor_sync(0xffffffffu, t0, off);
        float o1 = __shfl_xor_sync(0xffffffffu, t1, off);
        float o2 = __shfl_xor_sync(0xffffffffu, t2, off);
        float o3 = __shfl_xor_sync(0xffffffffu, t3, off);
        float o4 = __shfl_xor_sync(0xffffffffu, t4, off);
        ins5(o0, t0, t1, t2, t3, t4);
        ins5(o1, t0, t1, t2, t3, t4);
        ins5(o2, t0, t1, t2, t3, t4);
        ins5(o3, t0, t1, t2, t3, t4);
        ins5(o4, t0, t1, t2, t3, t4);
    }
    if (lane == 0) {
        float rho = t0;
        g_rhou[col] = rho;
        g_colsum[col] = 0.f;
        float a1 = fmaxf(t1 - rho, 0.f), a2 = fmaxf(t2 - rho, 0.f);
        float a3 = fmaxf(t3 - rho, 0.f), a4 = fmaxf(t4 - rho, 0.f);
        g_sigu[col] = calibrate(a1, a2, a3, a4, TARGET_U);
    }
}

// ---------------- K3: merge row halves + sigma_z ------------------------------
__global__ __launch_bounds__(256) void k_sigz() {
    int row = blockIdx.x * 256 + threadIdx.x;
    const float* p0 = g_rowp + (size_t)row * 5;
    const float* p1 = g_rowp + (size_t)NROWS * 5 + (size_t)row * 5;
    float t0 = INF_F, t1 = INF_F, t2 = INF_F, t3 = INF_F, t4 = INF_F;
#pragma unroll
    for (int s = 0; s < 5; s++) ins5(p0[s], t0, t1, t2, t3, t4);
#pragma unroll
    for (int s = 0; s < 5; s++) ins5(p1[s], t0, t1, t2, t3, t4);
    float rho = t0;
    g_rhoz[row] = rho;
    float a1 = fmaxf(t1 - rho, 0.f), a2 = fmaxf(t2 - rho, 0.f);
    float a3 = fmaxf(t3 - rho, 0.f), a4 = fmaxf(t4 - rho, 0.f);
    g_sigz[row] = calibrate(a1, a2, a3, a4, TARGET_Z);
}

// ---------------- K4: W1 / W2 / S + colsum (warp per row) -------------------
__global__ __launch_bounds__(256) void k_ws(float* __restrict__ out) {
    __shared__ float s_rho[KC], s_isu[KC], s_cs[KC];
    int t = threadIdx.x;
    s_rho[t] = g_rhou[t];
    s_isu[t] = 1.0f / g_sigu[t];
    s_cs[t] = 0.f;
    __syncthreads();

    int lane = t & 31;
    int wid = (blockIdx.x << 3) + (t >> 5);
    float* outW1a = out;
    float* outS   = out + NKSZ;
    float* outW1b = out + 2 * NKSZ;
    const int wstride = gridDim.x << 3;

    for (int row = wid; row < NROWS; row += wstride) {
        float rho = g_rhoz[row];
        float isz = 1.0f / g_sigz[row];
        const float* dr = g_d + (size_t)row * KC;
        float w1v[8], sv[8];
        float sum = 0.f;
#pragma unroll
        for (int i = 0; i < 8; i++) {
            int c = lane + (i << 5);
            float v = dr[c];
            float w1 = __expf(-fmaxf(v - rho, 0.f) * isz);
            float w2 = __expf(-fmaxf(v - s_rho[c], 0.f) * s_isu[c]);
            float s = w1 + w2 - w1 * w2;
            w1v[i] = w1; sv[i] = s; sum += s;
        }
#pragma unroll
        for (int off = 16; off; off >>= 1) sum += __shfl_xor_sync(0xffffffffu, sum, off);
        float rinv = 1.0f / sum;
#pragma unroll
        for (int i = 0; i < 8; i++) {
            int c = lane + (i << 5);
            size_t idx = (size_t)row * KC + c;
            float S = sv[i] * rinv;
            outW1a[idx] = w1v[i];
            outW1b[idx] = w1v[i];
            outS[idx] = S;
            atomicAdd(&s_cs[c], S);
        }
    }
    __syncthreads();
    atomicAdd(&g_colsum[t], s_cs[t]);
}

// ---------------- K5: Dmat ---------------------------------------------------
__global__ __launch_bounds__(256) void k_dmat(float* __restrict__ out) {
    __shared__ float s_ic[KC];
    int t = threadIdx.x;
    s_ic[t] = 1.0f / g_colsum[t];
    __syncthreads();

    const float* Sm = out + NKSZ;
    float* Dm = out + 3 * NKSZ;
    int lane = t & 31;
    int wid = (blockIdx.x << 3) + (t >> 5);
    const int wstride = gridDim.x << 3;

    for (int row = wid; row < NROWS; row += wstride) {
        const float* sr = Sm + (size_t)row * KC;
        float tv[8];
        float sum = 0.f;
#pragma unroll
        for (int i = 0; i < 8; i++) {
            int c = lane + (i << 5);
            float S = sr[c];
            float q = S * S * s_ic[c];
            tv[i] = q; sum += q;
        }
#pragma unroll
        for (int off = 16; off; off >>= 1) sum += __shfl_xor_sync(0xffffffffu, sum, off);
        float rinv = 1.0f / sum;
#pragma unroll
        for (int i = 0; i < 8; i++) {
            int c = lane + (i << 5);
            Dm[(size_t)row * KC + c] = tv[i] * rinv;
        }
    }
}

// ---------------- launcher ---------------------------------------------------
extern "C" void kernel_launch(void* const* d_in, const int* in_sizes, int n_in,
                              void* d_out, int out_size) {
    (void)in_sizes; (void)n_in; (void)out_size;
    const float* z  = (const float*)d_in[0];
    const float* mu = (const float*)d_in[1];
    float* out = (float*)d_out;

    cudaFuncSetAttribute(k_gemm, cudaFuncAttributeMaxDynamicSharedMemorySize,
                         GSMEM_TOTAL);

    k_prep_mu<<<1, 256>>>(mu);
    k_gemm<<<dim3(NROWS / 128, 2), 512, GSMEM_TOTAL>>>(z);
    k_colfinal<<<KC, 32>>>();
    k_sigz<<<NROWS / 256, 256>>>();
    k_ws<<<1024, 256>>>(out);
    k_dmat<<<1024, 256>>>(out);
}

// round 7
// speedup vs baseline: 1.4250x; 1.4250x over previous
#include <cuda_runtime.h>
#include <cuda_bf16.h>
#include <math.h>
#include <stdint.h>

#define NROWS 65536
#define KC 256
#define DH 256
#define NKSZ ((size_t)NROWS * KC)
#define EPSV 1e-6f
#define SIGMA_HI_V 10000.0f
#define TARGET_Z 1.3219281f   /* log2(5)-1 */
#define TARGET_U 2.3219281f   /* log2(5)   */
#define INF_F __int_as_float(0x7f800000)
#define CAL_ITERS 64
#define NPART 512

// ---------------- scratch (device globals; no runtime allocation) ----------
__device__ float g_d[NKSZ];                 // 64MB distance matrix
__device__ uint4 g_mhi4[KC * 64];           // mu hi tf32-in-f32 (16B quads)
__device__ uint4 g_mlo4[KC * 64];           // mu lo tf32-in-f32
__device__ float g_m2[KC], g_ms[KC];
__device__ float g_relz[(size_t)NROWS * 5];
__device__ float g_rhoz[NROWS];
__device__ float g_sigz[NROWS];
__device__ float g_part1[NPART * 5 * KC];   // [cta][s][col]
__device__ float g_rhou[KC];
__device__ float g_sigu[KC];
__device__ float g_colsum[KC];

// ---------------- PTX helpers (baseline PTX only) ----------------------------
__device__ __forceinline__ uint32_t smem_u32(const void* p) {
    uint32_t a;
    asm("{ .reg .u64 t; cvta.to.shared.u64 t, %1; cvt.u32.u64 %0, t; }" : "=r"(a) : "l"(p));
    return a;
}

__device__ __forceinline__ uint32_t tf32u(float x) {
    uint32_t u;
    asm("cvt.rna.tf32.f32 %0, %1;" : "=r"(u) : "f"(x));
    return u;
}

__device__ __forceinline__ void ldmx4(uint32_t* r, uint32_t addr) {
    asm volatile("ldmatrix.sync.aligned.m8n8.x4.shared.b16 {%0,%1,%2,%3}, [%4];"
                 : "=r"(r[0]), "=r"(r[1]), "=r"(r[2]), "=r"(r[3]) : "r"(addr));
}

__device__ __forceinline__ void mma_tf32(float* d, const uint32_t* a, const uint32_t* b) {
    asm volatile(
        "mma.sync.aligned.m16n8k8.row.col.f32.tf32.tf32.f32 "
        "{%0,%1,%2,%3}, {%4,%5,%6,%7}, {%8,%9}, {%0,%1,%2,%3};"
        : "+f"(d[0]), "+f"(d[1]), "+f"(d[2]), "+f"(d[3])
        : "r"(a[0]), "r"(a[1]), "r"(a[2]), "r"(a[3]), "r"(b[0]), "r"(b[1]));
}

// ---------------- K0: mu prep (hi/lo tf32 split + stats) ---------------------
__global__ void k_prep_mu(const float* __restrict__ mu) {
    int j = threadIdx.x;
    const float* r = mu + (size_t)j * DH;
    float m2 = 0.f, ms = 0.f;
    for (int i = 0; i < 64; i++) {
        float4 v = *(const float4*)(r + i * 4);
        float x[4] = {v.x, v.y, v.z, v.w};
        uint32_t hi[4], lo[4];
#pragma unroll
        for (int q = 0; q < 4; q++) {
            m2 = fmaf(x[q], x[q], m2);
            ms += x[q];
            hi[q] = tf32u(x[q]);
            lo[q] = tf32u(x[q] - __uint_as_float(hi[q]));
        }
        g_mhi4[j * 64 + i] = make_uint4(hi[0], hi[1], hi[2], hi[3]);
        g_mlo4[j * 64 + i] = make_uint4(lo[0], lo[1], lo[2], lo[3]);
    }
    g_m2[j] = m2;
    g_ms[j] = ms;
}

// ---------------- insertion helper ------------------------------------------
__device__ __forceinline__ void ins5(float v, float &t0, float &t1, float &t2,
                                     float &t3, float &t4) {
    if (v < t4) {
        if (v < t3) {
            t4 = t3;
            if (v < t2) {
                t3 = t2;
                if (v < t1) {
                    t2 = t1;
                    if (v < t0) { t1 = t0; t0 = v; } else t1 = v;
                } else t2 = v;
            } else t3 = v;
        } else t4 = v;
    }
}

// ---------------- K1: fused tf32-split GEMM + d + row/col top5 ---------------
// CTA: 128 z-rows x 256 mu-cols, 512 threads = 16 warps (4x4).
// Warp tile 32x64. K in 8 chunks of 32; m16n8k8 tf32 mma, fp32 accum.
// 3 passes hh+lh+hl; B fragments STREAMED (4 regs at a time) to avoid spills.
#define LDS_A 36                      /* padded f32 row stride */
#define TILE_LD 260                   /* padded f32 tile stride */
#define SA_HI 0
#define SA_LO 18432
#define SB_HI 36864
#define SB_LO 73728
#define ST_M2 133120
#define ST_MS 134144
#define ST_Z2 135168
#define ST_ZS 135680
#define GSMEM_TOTAL 136192

__global__ __launch_bounds__(512, 1) void k_gemm(const float* __restrict__ z) {
    extern __shared__ char smem[];
    const uint32_t sb = smem_u32(smem);
    const int t = threadIdx.x;
    const int wid = t >> 5, lane = t & 31;
    const int wr = wid >> 2, wc = wid & 3;
    const int rowBase = blockIdx.x * 128;

    float* s_m2 = (float*)(smem + ST_M2);
    float* s_ms = (float*)(smem + ST_MS);
    float* s_z2 = (float*)(smem + ST_Z2);
    float* s_zs = (float*)(smem + ST_ZS);
    if (t < 256) { s_m2[t] = g_m2[t]; s_ms[t] = g_ms[t]; }

    float acc[2][8][4];
#pragma unroll
    for (int mt = 0; mt < 2; mt++)
#pragma unroll
        for (int j = 0; j < 8; j++)
#pragma unroll
            for (int q = 0; q < 4; q++) acc[mt][j][q] = 0.f;

    // A loader mapping: thread -> (row = t/4, 8-col segment aq = t%4)
    const int ar = t >> 2, aq = t & 3;
    const float* zrow = z + (size_t)(rowBase + ar) * DH + aq * 8;
    float z2p = 0.f, zsp = 0.f;

    // ldmatrix lane address components (f32 tiles: 8 rows x 4 f32-cols)
    const uint32_t a_off = ((uint32_t)(wr * 32 + (lane & 15)) * LDS_A +
                            ((lane >> 4) << 2)) * 4;
    const uint32_t b_off = ((uint32_t)(wc * 64 + ((lane >> 4) << 3) + (lane & 7)) * LDS_A +
                            ((lane & 8) >> 1)) * 4;

#pragma unroll 1
    for (int c = 0; c < 8; c++) {
        __syncthreads();
        // ---- A: load z fp32, split to hi/lo tf32, store to smem -------------
        {
            const float4* src = (const float4*)(zrow + c * 32);
            float4 v0 = src[0], v1 = src[1];
            float xs[8] = {v0.x, v0.y, v0.z, v0.w, v1.x, v1.y, v1.z, v1.w};
            float hi[8], lo[8];
#pragma unroll
            for (int q = 0; q < 8; q++) {
                z2p = fmaf(xs[q], xs[q], z2p);
                zsp += xs[q];
                uint32_t h = tf32u(xs[q]);
                hi[q] = __uint_as_float(h);
                lo[q] = __uint_as_float(tf32u(xs[q] - hi[q]));
            }
            uint32_t off = ((uint32_t)ar * LDS_A + aq * 8) * 4;
            *(float4*)(smem + SA_HI + off)      = make_float4(hi[0], hi[1], hi[2], hi[3]);
            *(float4*)(smem + SA_HI + off + 16) = make_float4(hi[4], hi[5], hi[6], hi[7]);
            *(float4*)(smem + SA_LO + off)      = make_float4(lo[0], lo[1], lo[2], lo[3]);
            *(float4*)(smem + SA_LO + off + 16) = make_float4(lo[4], lo[5], lo[6], lo[7]);
        }
        // ---- B: copy pre-converted mu hi/lo quads (256 rows x 8 uint4) ------
#pragma unroll
        for (int i = 0; i < 4; i++) {
            int e = t + 512 * i;             // 0..2047
            int row = e >> 3, q = e & 7;
            uint32_t off = ((uint32_t)row * LDS_A + q * 4) * 4;
            *(uint4*)(smem + SB_HI + off) = g_mhi4[row * 64 + c * 8 + q];
            *(uint4*)(smem + SB_LO + off) = g_mlo4[row * 64 + c * 8 + q];
        }
        __syncthreads();

        // ---- mma over 4 k8-steps, B streamed in 4-reg groups -----------------
#pragma unroll
        for (int ks = 0; ks < 4; ks++) {
            const uint32_t kb = (uint32_t)ks * 32;
            uint32_t ah[2][4], al[2][4];
            ldmx4(ah[0], sb + SA_HI + a_off + kb);
            ldmx4(ah[1], sb + SA_HI + a_off + kb + 16 * LDS_A * 4);
            ldmx4(al[0], sb + SA_LO + a_off + kb);
            ldmx4(al[1], sb + SA_LO + a_off + kb + 16 * LDS_A * 4);
#pragma unroll
            for (int p = 0; p < 4; p++) {
                const uint32_t pb = (uint32_t)p * 16 * LDS_A * 4;
                uint32_t bh[4];
                ldmx4(bh, sb + SB_HI + b_off + kb + pb);
                // hh pass
                mma_tf32(acc[0][2 * p],     ah[0], &bh[0]);
                mma_tf32(acc[0][2 * p + 1], ah[0], &bh[2]);
                mma_tf32(acc[1][2 * p],     ah[1], &bh[0]);
                mma_tf32(acc[1][2 * p + 1], ah[1], &bh[2]);
                // lh pass
                mma_tf32(acc[0][2 * p],     al[0], &bh[0]);
                mma_tf32(acc[0][2 * p + 1], al[0], &bh[2]);
                mma_tf32(acc[1][2 * p],     al[1], &bh[0]);
                mma_tf32(acc[1][2 * p + 1], al[1], &bh[2]);
                // hl pass
                uint32_t bl[4];
                ldmx4(bl, sb + SB_LO + b_off + kb + pb);
                mma_tf32(acc[0][2 * p],     ah[0], &bl[0]);
                mma_tf32(acc[0][2 * p + 1], ah[0], &bl[2]);
                mma_tf32(acc[1][2 * p],     ah[1], &bl[0]);
                mma_tf32(acc[1][2 * p + 1], ah[1], &bl[2]);
            }
        }
    }

    // ---- finalize per-row z stats (4 loader threads per row) ---------------
    z2p += __shfl_xor_sync(0xffffffffu, z2p, 1);
    z2p += __shfl_xor_sync(0xffffffffu, z2p, 2);
    zsp += __shfl_xor_sync(0xffffffffu, zsp, 1);
    zsp += __shfl_xor_sync(0xffffffffu, zsp, 2);
    if (aq == 0) { s_z2[ar] = z2p; s_zs[ar] = zsp; }
    __syncthreads();

    // ---- epilogue: d into smem tile (overwrites A/B buffers) ----------------
    float* tile = (float*)smem;
    const float cterm = (float)DH * EPSV * EPSV;
#pragma unroll
    for (int mt = 0; mt < 2; mt++) {
        const int r0 = wr * 32 + mt * 16 + (lane >> 2);
        const float z2va = s_z2[r0], zsva = s_zs[r0];
        const float z2vb = s_z2[r0 + 8], zsvb = s_zs[r0 + 8];
#pragma unroll
        for (int nt = 0; nt < 8; nt++) {
            const int c0 = wc * 64 + nt * 8 + (lane & 3) * 2;
            float m20 = s_m2[c0], ms0 = s_ms[c0];
            float m21 = s_m2[c0 + 1], ms1 = s_ms[c0 + 1];
            float d00 = z2va + m20 - 2.f * acc[mt][nt][0] + 2.f * EPSV * (zsva - ms0) + cterm;
            float d01 = z2va + m21 - 2.f * acc[mt][nt][1] + 2.f * EPSV * (zsva - ms1) + cterm;
            float d10 = z2vb + m20 - 2.f * acc[mt][nt][2] + 2.f * EPSV * (zsvb - ms0) + cterm;
            float d11 = z2vb + m21 - 2.f * acc[mt][nt][3] + 2.f * EPSV * (zsvb - ms1) + cterm;
            tile[r0 * TILE_LD + c0]           = sqrtf(fmaxf(d00, 0.f));
            tile[r0 * TILE_LD + c0 + 1]       = sqrtf(fmaxf(d01, 0.f));
            tile[(r0 + 8) * TILE_LD + c0]     = sqrtf(fmaxf(d10, 0.f));
            tile[(r0 + 8) * TILE_LD + c0 + 1] = sqrtf(fmaxf(d11, 0.f));
        }
    }
    __syncthreads();

    // ---- coalesced store of d ------------------------------------------------
#pragma unroll
    for (int i = 0; i < 16; i++) {
        int e = t + 512 * i;          // 0..8191
        int row = e >> 6, c4 = e & 63;
        float4 v = *(const float4*)&tile[row * TILE_LD + c4 * 4];
        *(float4*)&g_d[(size_t)(rowBase + row) * KC + c4 * 4] = v;
    }

    // ---- fused row top-5 (warp per 8 rows) -----------------------------------
#pragma unroll 1
    for (int rr = 0; rr < 8; rr++) {
        int lrow = wid * 8 + rr;
        float t0 = INF_F, t1 = INF_F, t2 = INF_F, t3 = INF_F, t4 = INF_F;
#pragma unroll
        for (int i = 0; i < 8; i++)
            ins5(tile[lrow * TILE_LD + lane + 32 * i], t0, t1, t2, t3, t4);
#pragma unroll
        for (int off = 16; off; off >>= 1) {
            float o0 = __shfl_xor_sync(0xffffffffu, t0, off);
            float o1 = __shfl_xor_sync(0xffffffffu, t1, off);
            float o2 = __shfl_xor_sync(0xffffffffu, t2, off);
            float o3 = __shfl_xor_sync(0xffffffffu, t3, off);
            float o4 = __shfl_xor_sync(0xffffffffu, t4, off);
            ins5(o0, t0, t1, t2, t3, t4);
            ins5(o1, t0, t1, t2, t3, t4);
            ins5(o2, t0, t1, t2, t3, t4);
            ins5(o3, t0, t1, t2, t3, t4);
            ins5(o4, t0, t1, t2, t3, t4);
        }
        if (lane == 0) {
            int grow = rowBase + lrow;
            g_rhoz[grow] = t0;
            float* rp = g_relz + (size_t)grow * 5;
            rp[0] = t0; rp[1] = t1; rp[2] = t2; rp[3] = t3; rp[4] = t4;
        }
    }

    // ---- fused per-CTA column top-5 partials ---------------------------------
    if (t < 256) {
        float t0 = INF_F, t1 = INF_F, t2 = INF_F, t3 = INF_F, t4 = INF_F;
#pragma unroll 4
        for (int r = 0; r < 128; r++)
            ins5(tile[r * TILE_LD + t], t0, t1, t2, t3, t4);
        float* pp = g_part1 + (size_t)blockIdx.x * 5 * KC + t;
        pp[0 * KC] = t0; pp[1 * KC] = t1; pp[2 * KC] = t2;
        pp[3 * KC] = t3; pp[4 * KC] = t4;
    }
}

// ---------------- bisection (mirrors reference update rule) -----------------
__device__ __forceinline__ float calibrate(float a1, float a2, float a3, float a4,
                                           float target) {
    float mid0 = 0.f, mid1 = SIGMA_HI_V, sigma = 1.f;
#pragma unroll 1
    for (int it = 0; it < CAL_ITERS; it++) {
        float inv = __frcp_rn(sigma);
        float cur = 1.f + __expf(-a1 * inv) + __expf(-a2 * inv) +
                    __expf(-a3 * inv) + __expf(-a4 * inv);
        if (cur > target) mid1 = sigma; else mid0 = sigma;
        sigma = 0.5f * (mid0 + mid1);
    }
    return sigma;
}

// ---------------- K2: final column merge + sigma_u (+ colsum zero) ----------
__global__ void k_colfinal() {
    int col = blockIdx.x;
    int lane = threadIdx.x;  // 32 threads
    float t0 = INF_F, t1 = INF_F, t2 = INF_F, t3 = INF_F, t4 = INF_F;
    for (int b = lane; b < NPART; b += 32) {
        const float* pp = g_part1 + (size_t)b * 5 * KC + col;
#pragma unroll
        for (int s = 0; s < 5; s++) ins5(pp[s * KC], t0, t1, t2, t3, t4);
    }
#pragma unroll
    for (int off = 16; off; off >>= 1) {
        float o0 = __shfl_xor_sync(0xffffffffu, t0, off);
        float o1 = __shfl_xor_sync(0xffffffffu, t1, off);
        float o2 = __shfl_xor_sync(0xffffffffu, t2, off);
        float o3 = __shfl_xor_sync(0xffffffffu, t3, off);
        float o4 = __shfl_xor_sync(0xffffffffu, t4, off);
        ins5(o0, t0, t1, t2, t3, t4);
        ins5(o1, t0, t1, t2, t3, t4);
        ins5(o2, t0, t1, t2, t3, t4);
        ins5(o3, t0, t1, t2, t3, t4);
        ins5(o4, t0, t1, t2, t3, t4);
    }
    if (lane == 0) {
        float rho = t0;
        g_rhou[col] = rho;
        g_colsum[col] = 0.f;
        float a1 = fmaxf(t1 - rho, 0.f), a2 = fmaxf(t2 - rho, 0.f);
        float a3 = fmaxf(t3 - rho, 0.f), a4 = fmaxf(t4 - rho, 0.f);
        g_sigu[col] = calibrate(a1, a2, a3, a4, TARGET_U);
    }
}

// ---------------- K3: sigma_z (thread per row) ------------------------------
__global__ __launch_bounds__(256) void k_sigz() {
    int row = blockIdx.x * 256 + threadIdx.x;
    const float* r = g_relz + (size_t)row * 5;
    float rho = r[0];
    float a1 = fmaxf(r[1] - rho, 0.f), a2 = fmaxf(r[2] - rho, 0.f);
    float a3 = fmaxf(r[3] - rho, 0.f), a4 = fmaxf(r[4] - rho, 0.f);
    g_sigz[row] = calibrate(a1, a2, a3, a4, TARGET_Z);
}

// ---------------- K4: W1 / W2 / S + colsum (warp per row) -------------------
__global__ __launch_bounds__(256) void k_ws(float* __restrict__ out) {
    __shared__ float s_rho[KC], s_isu[KC], s_cs[KC];
    int t = threadIdx.x;
    s_rho[t] = g_rhou[t];
    s_isu[t] = 1.0f / g_sigu[t];
    s_cs[t] = 0.f;
    __syncthreads();

    int lane = t & 31;
    int wid = (blockIdx.x << 3) + (t >> 5);
    float* outW1a = out;
    float* outS   = out + NKSZ;
    float* outW1b = out + 2 * NKSZ;
    const int wstride = gridDim.x << 3;

    for (int row = wid; row < NROWS; row += wstride) {
        float rho = g_rhoz[row];
        float isz = 1.0f / g_sigz[row];
        const float* dr = g_d + (size_t)row * KC;
        float w1v[8], sv[8];
        float sum = 0.f;
#pragma unroll
        for (int i = 0; i < 8; i++) {
            int c = lane + (i << 5);
            float v = dr[c];
            float w1 = __expf(-fmaxf(v - rho, 0.f) * isz);
            float w2 = __expf(-fmaxf(v - s_rho[c], 0.f) * s_isu[c]);
            float s = w1 + w2 - w1 * w2;
            w1v[i] = w1; sv[i] = s; sum += s;
        }
#pragma unroll
        for (int off = 16; off; off >>= 1) sum += __shfl_xor_sync(0xffffffffu, sum, off);
        float rinv = 1.0f / sum;
#pragma unroll
        for (int i = 0; i < 8; i++) {
            int c = lane + (i << 5);
            size_t idx = (size_t)row * KC + c;
            float S = sv[i] * rinv;
            outW1a[idx] = w1v[i];
            outW1b[idx] = w1v[i];
            outS[idx] = S;
            atomicAdd(&s_cs[c], S);
        }
    }
    __syncthreads();
    atomicAdd(&g_colsum[t], s_cs[t]);
}

// ---------------- K5: Dmat ---------------------------------------------------
__global__ __launch_bounds__(256) void k_dmat(float* __restrict__ out) {
    __shared__ float s_ic[KC];
    int t = threadIdx.x;
    s_ic[t] = 1.0f / g_colsum[t];
    __syncthreads();

    const float* Sm = out + NKSZ;
    float* Dm = out + 3 * NKSZ;
    int lane = t & 31;
    int wid = (blockIdx.x << 3) + (t >> 5);
    const int wstride = gridDim.x << 3;

    for (int row = wid; row < NROWS; row += wstride) {
        const float* sr = Sm + (size_t)row * KC;
        float tv[8];
        float sum = 0.f;
#pragma unroll
        for (int i = 0; i < 8; i++) {
            int c = lane + (i << 5);
            float S = sr[c];
            float q = S * S * s_ic[c];
            tv[i] = q; sum += q;
        }
#pragma unroll
        for (int off = 16; off; off >>= 1) sum += __shfl_xor_sync(0xffffffffu, sum, off);
        float rinv = 1.0f / sum;
#pragma unroll
        for (int i = 0; i < 8; i++) {
            int c = lane + (i << 5);
            Dm[(size_t)row * KC + c] = tv[i] * rinv;
        }
    }
}

// ---------------- launcher ---------------------------------------------------
extern "C" void kernel_launch(void* const* d_in, const int* in_sizes, int n_in,
                              void* d_out, int out_size) {
    (void)in_sizes; (void)n_in; (void)out_size;
    const float* z  = (const float*)d_in[0];
    const float* mu = (const float*)d_in[1];
    float* out = (float*)d_out;

    cudaFuncSetAttribute(k_gemm, cudaFuncAttributeMaxDynamicSharedMemorySize,
                         GSMEM_TOTAL);

    k_prep_mu<<<1, 256>>>(mu);
    k_gemm<<<NROWS / 128, 512, GSMEM_TOTAL>>>(z);
    k_colfinal<<<KC, 32>>>();
    k_sigz<<<NROWS / 256, 256>>>();
    k_ws<<<1024, 256>>>(out);
    k_dmat<<<1024, 256>>>(out);
}

// round 8
// speedup vs baseline: 1.4288x; 1.0026x over previous
#include <cuda_runtime.h>
#include <cuda_bf16.h>
#include <math.h>
#include <stdint.h>

#define NROWS 65536
#define KC 256
#define DH 256
#define NKSZ ((size_t)NROWS * KC)
#define EPSV 1e-6f
#define SIGMA_HI_V 10000.0f
#define TARGET_Z 1.3219281f   /* log2(5)-1 */
#define TARGET_U 2.3219281f   /* log2(5)   */
#define INF_F __int_as_float(0x7f800000)
#define CAL_ITERS 64
#define NPART 512

// ---------------- scratch (device globals; no runtime allocation) ----------
__device__ float g_d[NKSZ];                 // 64MB distance matrix
__device__ uint4 g_mhi4[KC * 64];           // mu hi tf32-in-f32 (16B quads)
__device__ uint4 g_mlo4[KC * 64];           // mu lo tf32-in-f32
__device__ float g_m2[KC], g_ms[KC];
__device__ float g_relz[(size_t)NROWS * 5];
__device__ float g_rhoz[NROWS];
__device__ float g_sigz[NROWS];
__device__ float g_part1[NPART * 5 * KC];   // [cta][s][col]
__device__ float g_rhou[KC];
__device__ float g_sigu[KC];
__device__ float g_colsum[KC];

// ---------------- PTX helpers (baseline PTX only) ----------------------------
__device__ __forceinline__ uint32_t smem_u32(const void* p) {
    uint32_t a;
    asm("{ .reg .u64 t; cvta.to.shared.u64 t, %1; cvt.u32.u64 %0, t; }" : "=r"(a) : "l"(p));
    return a;
}

__device__ __forceinline__ uint32_t tf32u(float x) {
    uint32_t u;
    asm("cvt.rna.tf32.f32 %0, %1;" : "=r"(u) : "f"(x));
    return u;
}

__device__ __forceinline__ void ldmx4(uint32_t* r, uint32_t addr) {
    asm volatile("ldmatrix.sync.aligned.m8n8.x4.shared.b16 {%0,%1,%2,%3}, [%4];"
                 : "=r"(r[0]), "=r"(r[1]), "=r"(r[2]), "=r"(r[3]) : "r"(addr));
}

__device__ __forceinline__ void mma_tf32(float* d, const uint32_t* a, const uint32_t* b) {
    asm volatile(
        "mma.sync.aligned.m16n8k8.row.col.f32.tf32.tf32.f32 "
        "{%0,%1,%2,%3}, {%4,%5,%6,%7}, {%8,%9}, {%0,%1,%2,%3};"
        : "+f"(d[0]), "+f"(d[1]), "+f"(d[2]), "+f"(d[3])
        : "r"(a[0]), "r"(a[1]), "r"(a[2]), "r"(a[3]), "r"(b[0]), "r"(b[1]));
}

// ---------------- K0: mu prep (hi/lo tf32 split + stats) ---------------------
__global__ void k_prep_mu(const float* __restrict__ mu) {
    int j = threadIdx.x;
    const float* r = mu + (size_t)j * DH;
    float m2 = 0.f, ms = 0.f;
    for (int i = 0; i < 64; i++) {
        float4 v = *(const float4*)(r + i * 4);
        float x[4] = {v.x, v.y, v.z, v.w};
        uint32_t hi[4], lo[4];
#pragma unroll
        for (int q = 0; q < 4; q++) {
            m2 = fmaf(x[q], x[q], m2);
            ms += x[q];
            hi[q] = tf32u(x[q]);
            lo[q] = tf32u(x[q] - __uint_as_float(hi[q]));
        }
        g_mhi4[j * 64 + i] = make_uint4(hi[0], hi[1], hi[2], hi[3]);
        g_mlo4[j * 64 + i] = make_uint4(lo[0], lo[1], lo[2], lo[3]);
    }
    g_m2[j] = m2;
    g_ms[j] = ms;
}

// ---------------- K-zero / K-noop (also pad launch order for profiling) -----
__global__ void k_zero() { g_colsum[threadIdx.x] = 0.f; }
__global__ void k_noop() {}

// ---------------- insertion helper ------------------------------------------
__device__ __forceinline__ void ins5(float v, float &t0, float &t1, float &t2,
                                     float &t3, float &t4) {
    if (v < t4) {
        if (v < t3) {
            t4 = t3;
            if (v < t2) {
                t3 = t2;
                if (v < t1) {
                    t2 = t1;
                    if (v < t0) { t1 = t0; t0 = v; } else t1 = v;
                } else t2 = v;
            } else t3 = v;
        } else t4 = v;
    }
}

// ---------------- K1: fused tf32-split GEMM + d + row/col top5 ---------------
// CTA: 128 z-rows x 256 mu-cols, 512 threads = 16 warps (4x4).
// Warp tile 32x64. K in 4 chunks of 64; m16n8k8 tf32 mma, fp32 accum.
// 3 passes hh+lh+hl; B fragments streamed (4 regs at a time).
#define LDS_A 68                      /* padded f32 row stride (64+4) */
#define TILE_LD 260                   /* padded f32 tile stride */
#define SA_HI 0
#define SA_LO 34816
#define SB_HI 69632
#define SB_LO 139264
#define ST_M2 208896
#define ST_MS 209920
#define ST_Z2 210944
#define ST_ZS 211456
#define GSMEM_TOTAL 211968

__global__ __launch_bounds__(512, 1) void k_gemm(const float* __restrict__ z) {
    extern __shared__ char smem[];
    const uint32_t sb = smem_u32(smem);
    const int t = threadIdx.x;
    const int wid = t >> 5, lane = t & 31;
    const int wr = wid >> 2, wc = wid & 3;
    const int rowBase = blockIdx.x * 128;

    float* s_m2 = (float*)(smem + ST_M2);
    float* s_ms = (float*)(smem + ST_MS);
    float* s_z2 = (float*)(smem + ST_Z2);
    float* s_zs = (float*)(smem + ST_ZS);
    if (t < 256) { s_m2[t] = g_m2[t]; s_ms[t] = g_ms[t]; }

    float acc[2][8][4];
#pragma unroll
    for (int mt = 0; mt < 2; mt++)
#pragma unroll
        for (int j = 0; j < 8; j++)
#pragma unroll
            for (int q = 0; q < 4; q++) acc[mt][j][q] = 0.f;

    // A loader mapping: thread -> (row = t/4, 16-col segment aq = t%4)
    const int ar = t >> 2, aq = t & 3;
    const float* zrow = z + (size_t)(rowBase + ar) * DH + aq * 16;
    float z2p = 0.f, zsp = 0.f;

    // ldmatrix lane address components (f32 tiles: 8 rows x 4 f32-cols)
    const uint32_t a_off = ((uint32_t)(wr * 32 + (lane & 15)) * LDS_A +
                            ((lane >> 4) << 2)) * 4;
    const uint32_t b_off = ((uint32_t)(wc * 64 + ((lane >> 4) << 3) + (lane & 7)) * LDS_A +
                            ((lane & 8) >> 1)) * 4;

#pragma unroll 1
    for (int c = 0; c < 4; c++) {
        __syncthreads();
        // ---- A: load z fp32 (16 f32/thread), split to hi/lo tf32 ------------
        {
            const float4* src = (const float4*)(zrow + c * 64);
            float4 v0 = src[0], v1 = src[1], v2 = src[2], v3 = src[3];
            float xs[16] = {v0.x, v0.y, v0.z, v0.w, v1.x, v1.y, v1.z, v1.w,
                            v2.x, v2.y, v2.z, v2.w, v3.x, v3.y, v3.z, v3.w};
            float hi[16], lo[16];
#pragma unroll
            for (int q = 0; q < 16; q++) {
                z2p = fmaf(xs[q], xs[q], z2p);
                zsp += xs[q];
                uint32_t h = tf32u(xs[q]);
                hi[q] = __uint_as_float(h);
                lo[q] = __uint_as_float(tf32u(xs[q] - hi[q]));
            }
            uint32_t off = ((uint32_t)ar * LDS_A + aq * 16) * 4;
#pragma unroll
            for (int g = 0; g < 4; g++) {
                *(float4*)(smem + SA_HI + off + g * 16) =
                    make_float4(hi[4 * g], hi[4 * g + 1], hi[4 * g + 2], hi[4 * g + 3]);
                *(float4*)(smem + SA_LO + off + g * 16) =
                    make_float4(lo[4 * g], lo[4 * g + 1], lo[4 * g + 2], lo[4 * g + 3]);
            }
        }
        // ---- B: copy pre-converted mu hi/lo quads (256 rows x 16 uint4) -----
#pragma unroll
        for (int i = 0; i < 8; i++) {
            int e = t + 512 * i;             // 0..4095
            int row = e >> 4, q = e & 15;
            uint32_t off = ((uint32_t)row * LDS_A + q * 4) * 4;
            *(uint4*)(smem + SB_HI + off) = g_mhi4[row * 64 + c * 16 + q];
            *(uint4*)(smem + SB_LO + off) = g_mlo4[row * 64 + c * 16 + q];
        }
        __syncthreads();

        // ---- mma over 8 k8-steps, B streamed in 4-reg groups -----------------
#pragma unroll
        for (int ks = 0; ks < 8; ks++) {
            const uint32_t kb = (uint32_t)ks * 32;
            uint32_t ah[2][4], al[2][4];
            ldmx4(ah[0], sb + SA_HI + a_off + kb);
            ldmx4(ah[1], sb + SA_HI + a_off + kb + 16 * LDS_A * 4);
            ldmx4(al[0], sb + SA_LO + a_off + kb);
            ldmx4(al[1], sb + SA_LO + a_off + kb + 16 * LDS_A * 4);
#pragma unroll
            for (int p = 0; p < 4; p++) {
                const uint32_t pb = (uint32_t)p * 16 * LDS_A * 4;
                uint32_t bh[4];
                ldmx4(bh, sb + SB_HI + b_off + kb + pb);
                mma_tf32(acc[0][2 * p],     ah[0], &bh[0]);
                mma_tf32(acc[0][2 * p + 1], ah[0], &bh[2]);
                mma_tf32(acc[1][2 * p],     ah[1], &bh[0]);
                mma_tf32(acc[1][2 * p + 1], ah[1], &bh[2]);
                mma_tf32(acc[0][2 * p],     al[0], &bh[0]);
                mma_tf32(acc[0][2 * p + 1], al[0], &bh[2]);
                mma_tf32(acc[1][2 * p],     al[1], &bh[0]);
                mma_tf32(acc[1][2 * p + 1], al[1], &bh[2]);
                uint32_t bl[4];
                ldmx4(bl, sb + SB_LO + b_off + kb + pb);
                mma_tf32(acc[0][2 * p],     ah[0], &bl[0]);
                mma_tf32(acc[0][2 * p + 1], ah[0], &bl[2]);
                mma_tf32(acc[1][2 * p],     ah[1], &bl[0]);
                mma_tf32(acc[1][2 * p + 1], ah[1], &bl[2]);
            }
        }
    }

    // ---- finalize per-row z stats (4 loader threads per row) ---------------
    z2p += __shfl_xor_sync(0xffffffffu, z2p, 1);
    z2p += __shfl_xor_sync(0xffffffffu, z2p, 2);
    zsp += __shfl_xor_sync(0xffffffffu, zsp, 1);
    zsp += __shfl_xor_sync(0xffffffffu, zsp, 2);
    if (aq == 0) { s_z2[ar] = z2p; s_zs[ar] = zsp; }
    __syncthreads();

    // ---- epilogue: d into smem tile (overwrites A/B buffers) ----------------
    float* tile = (float*)smem;
    const float cterm = (float)DH * EPSV * EPSV;
#pragma unroll
    for (int mt = 0; mt < 2; mt++) {
        const int r0 = wr * 32 + mt * 16 + (lane >> 2);
        const float z2va = s_z2[r0], zsva = s_zs[r0];
        const float z2vb = s_z2[r0 + 8], zsvb = s_zs[r0 + 8];
#pragma unroll
        for (int nt = 0; nt < 8; nt++) {
            const int c0 = wc * 64 + nt * 8 + (lane & 3) * 2;
            float m20 = s_m2[c0], ms0 = s_ms[c0];
            float m21 = s_m2[c0 + 1], ms1 = s_ms[c0 + 1];
            float d00 = z2va + m20 - 2.f * acc[mt][nt][0] + 2.f * EPSV * (zsva - ms0) + cterm;
            float d01 = z2va + m21 - 2.f * acc[mt][nt][1] + 2.f * EPSV * (zsva - ms1) + cterm;
            float d10 = z2vb + m20 - 2.f * acc[mt][nt][2] + 2.f * EPSV * (zsvb - ms0) + cterm;
            float d11 = z2vb + m21 - 2.f * acc[mt][nt][3] + 2.f * EPSV * (zsvb - ms1) + cterm;
            tile[r0 * TILE_LD + c0]           = sqrtf(fmaxf(d00, 0.f));
            tile[r0 * TILE_LD + c0 + 1]       = sqrtf(fmaxf(d01, 0.f));
            tile[(r0 + 8) * TILE_LD + c0]     = sqrtf(fmaxf(d10, 0.f));
            tile[(r0 + 8) * TILE_LD + c0 + 1] = sqrtf(fmaxf(d11, 0.f));
        }
    }
    __syncthreads();

    // ---- coalesced store of d ------------------------------------------------
#pragma unroll
    for (int i = 0; i < 16; i++) {
        int e = t + 512 * i;          // 0..8191
        int row = e >> 6, c4 = e & 63;
        float4 v = *(const float4*)&tile[row * TILE_LD + c4 * 4];
        *(float4*)&g_d[(size_t)(rowBase + row) * KC + c4 * 4] = v;
    }

    // ---- fused row top-5 (warp per 8 rows) -----------------------------------
#pragma unroll 1
    for (int rr = 0; rr < 8; rr++) {
        int lrow = wid * 8 + rr;
        float t0 = INF_F, t1 = INF_F, t2 = INF_F, t3 = INF_F, t4 = INF_F;
#pragma unroll
        for (int i = 0; i < 8; i++)
            ins5(tile[lrow * TILE_LD + lane + 32 * i], t0, t1, t2, t3, t4);
#pragma unroll
        for (int off = 16; off; off >>= 1) {
            float o0 = __shfl_xor_sync(0xffffffffu, t0, off);
            float o1 = __shfl_xor_sync(0xffffffffu, t1, off);
            float o2 = __shfl_xor_sync(0xffffffffu, t2, off);
            float o3 = __shfl_xor_sync(0xffffffffu, t3, off);
            float o4 = __shfl_xor_sync(0xffffffffu, t4, off);
            ins5(o0, t0, t1, t2, t3, t4);
            ins5(o1, t0, t1, t2, t3, t4);
            ins5(o2, t0, t1, t2, t3, t4);
            ins5(o3, t0, t1, t2, t3, t4);
            ins5(o4, t0, t1, t2, t3, t4);
        }
        if (lane == 0) {
            int grow = rowBase + lrow;
            g_rhoz[grow] = t0;
            float* rp = g_relz + (size_t)grow * 5;
            rp[0] = t0; rp[1] = t1; rp[2] = t2; rp[3] = t3; rp[4] = t4;
        }
    }

    // ---- fused per-CTA column top-5 partials ---------------------------------
    if (t < 256) {
        float t0 = INF_F, t1 = INF_F, t2 = INF_F, t3 = INF_F, t4 = INF_F;
#pragma unroll 4
        for (int r = 0; r < 128; r++)
            ins5(tile[r * TILE_LD + t], t0, t1, t2, t3, t4);
        float* pp = g_part1 + (size_t)blockIdx.x * 5 * KC + t;
        pp[0 * KC] = t0; pp[1 * KC] = t1; pp[2 * KC] = t2;
        pp[3 * KC] = t3; pp[4 * KC] = t4;
    }
}

// ---------------- bisection (mirrors reference update rule) -----------------
__device__ __forceinline__ float calibrate(float a1, float a2, float a3, float a4,
                                           float target) {
    float mid0 = 0.f, mid1 = SIGMA_HI_V, sigma = 1.f;
#pragma unroll 1
    for (int it = 0; it < CAL_ITERS; it++) {
        float inv = __frcp_rn(sigma);
        float cur = 1.f + __expf(-a1 * inv) + __expf(-a2 * inv) +
                    __expf(-a3 * inv) + __expf(-a4 * inv);
        if (cur > target) mid1 = sigma; else mid0 = sigma;
        sigma = 0.5f * (mid0 + mid1);
    }
    return sigma;
}

// ---------------- K2: final column merge + sigma_u ---------------------------
__global__ void k_colfinal() {
    int col = blockIdx.x;
    int lane = threadIdx.x;  // 32 threads
    float t0 = INF_F, t1 = INF_F, t2 = INF_F, t3 = INF_F, t4 = INF_F;
    for (int b = lane; b < NPART; b += 32) {
        const float* pp = g_part1 + (size_t)b * 5 * KC + col;
#pragma unroll
        for (int s = 0; s < 5; s++) ins5(pp[s * KC], t0, t1, t2, t3, t4);
    }
#pragma unroll
    for (int off = 16; off; off >>= 1) {
        float o0 = __shfl_xor_sync(0xffffffffu, t0, off);
        float o1 = __shfl_xor_sync(0xffffffffu, t1, off);
        float o2 = __shfl_xor_sync(0xffffffffu, t2, off);
        float o3 = __shfl_xor_sync(0xffffffffu, t3, off);
        float o4 = __shfl_xor_sync(0xffffffffu, t4, off);
        ins5(o0, t0, t1, t2, t3, t4);
        ins5(o1, t0, t1, t2, t3, t4);
        ins5(o2, t0, t1, t2, t3, t4);
        ins5(o3, t0, t1, t2, t3, t4);
        ins5(o4, t0, t1, t2, t3, t4);
    }
    if (lane == 0) {
        float rho = t0;
        g_rhou[col] = rho;
        float a1 = fmaxf(t1 - rho, 0.f), a2 = fmaxf(t2 - rho, 0.f);
        float a3 = fmaxf(t3 - rho, 0.f), a4 = fmaxf(t4 - rho, 0.f);
        g_sigu[col] = calibrate(a1, a2, a3, a4, TARGET_U);
    }
}

// ---------------- K3: sigma_z (thread per row) ------------------------------
__global__ __launch_bounds__(256) void k_sigz() {
    int row = blockIdx.x * 256 + threadIdx.x;
    const float* r = g_relz + (size_t)row * 5;
    float rho = r[0];
    float a1 = fmaxf(r[1] - rho, 0.f), a2 = fmaxf(r[2] - rho, 0.f);
    float a3 = fmaxf(r[3] - rho, 0.f), a4 = fmaxf(r[4] - rho, 0.f);
    g_sigz[row] = calibrate(a1, a2, a3, a4, TARGET_Z);
}

// ---------------- K4: W1 / W2 / S + colsum (warp per row) -------------------
__global__ __launch_bounds__(256) void k_ws(float* __restrict__ out) {
    __shared__ float s_rho[KC], s_isu[KC], s_cs[KC];
    int t = threadIdx.x;
    s_rho[t] = g_rhou[t];
    s_isu[t] = 1.0f / g_sigu[t];
    s_cs[t] = 0.f;
    __syncthreads();

    int lane = t & 31;
    int wid = (blockIdx.x << 3) + (t >> 5);
    float* outW1a = out;
    float* outS   = out + NKSZ;
    float* outW1b = out + 2 * NKSZ;
    const int wstride = gridDim.x << 3;

    for (int row = wid; row < NROWS; row += wstride) {
        float rho = g_rhoz[row];
        float isz = 1.0f / g_sigz[row];
        const float* dr = g_d + (size_t)row * KC;
        float w1v[8], sv[8];
        float sum = 0.f;
#pragma unroll
        for (int i = 0; i < 8; i++) {
            int c = lane + (i << 5);
            float v = dr[c];
            float w1 = __expf(-fmaxf(v - rho, 0.f) * isz);
            float w2 = __expf(-fmaxf(v - s_rho[c], 0.f) * s_isu[c]);
            float s = w1 + w2 - w1 * w2;
            w1v[i] = w1; sv[i] = s; sum += s;
        }
#pragma unroll
        for (int off = 16; off; off >>= 1) sum += __shfl_xor_sync(0xffffffffu, sum, off);
        float rinv = 1.0f / sum;
#pragma unroll
        for (int i = 0; i < 8; i++) {
            int c = lane + (i << 5);
            size_t idx = (size_t)row * KC + c;
            float S = sv[i] * rinv;
            outW1a[idx] = w1v[i];
            outW1b[idx] = w1v[i];
            outS[idx] = S;
            atomicAdd(&s_cs[c], S);
        }
    }
    __syncthreads();
    atomicAdd(&g_colsum[t], s_cs[t]);
}

// ---------------- K5: Dmat ---------------------------------------------------
__global__ __launch_bounds__(256) void k_dmat(float* __restrict__ out) {
    __shared__ float s_ic[KC];
    int t = threadIdx.x;
    s_ic[t] = 1.0f / g_colsum[t];
    __syncthreads();

    const float* Sm = out + NKSZ;
    float* Dm = out + 3 * NKSZ;
    int lane = t & 31;
    int wid = (blockIdx.x << 3) + (t >> 5);
    const int wstride = gridDim.x << 3;

    for (int row = wid; row < NROWS; row += wstride) {
        const float* sr = Sm + (size_t)row * KC;
        float tv[8];
        float sum = 0.f;
#pragma unroll
        for (int i = 0; i < 8; i++) {
            int c = lane + (i << 5);
            float S = sr[c];
            float q = S * S * s_ic[c];
            tv[i] = q; sum += q;
        }
#pragma unroll
        for (int off = 16; off; off >>= 1) sum += __shfl_xor_sync(0xffffffffu, sum, off);
        float rinv = 1.0f / sum;
#pragma unroll
        for (int i = 0; i < 8; i++) {
            int c = lane + (i << 5);
            Dm[(size_t)row * KC + c] = tv[i] * rinv;
        }
    }
}

// ---------------- launcher ---------------------------------------------------
extern "C" void kernel_launch(void* const* d_in, const int* in_sizes, int n_in,
                              void* d_out, int out_size) {
    (void)in_sizes; (void)n_in; (void)out_size;
    const float* z  = (const float*)d_in[0];
    const float* mu = (const float*)d_in[1];
    float* out = (float*)d_out;

    cudaFuncSetAttribute(k_gemm, cudaFuncAttributeMaxDynamicSharedMemorySize,
                         GSMEM_TOTAL);

    k_prep_mu<<<1, 256>>>(mu);       // #1
    k_zero<<<1, 256>>>();            // #2
    k_noop<<<1, 32>>>();             // #3
    k_gemm<<<NROWS / 128, 512, GSMEM_TOTAL>>>(z);   // #4 <- ncu slot
    k_colfinal<<<KC, 32>>>();        // #5
    k_sigz<<<NROWS / 256, 256>>>();  // #6
    k_ws<<<1024, 256>>>(out);        // #7
    k_dmat<<<1024, 256>>>(out);      // #8
}